// round 5
// baseline (speedup 1.0000x reference)
#include <cuda_runtime.h>
#include <cstdint>

// embedding_bag(mode='mean'): B bags over a [V,64] fp32 table.
// One HALF-WARP per bag; sublane s (0..15) owns one float4 (cols 4s..4s+3).
// A warp's LDG.E.128 covers two full 256B rows (one per half) = 512B.
// All of the CTA's indices are staged in shared memory as u32 BYTE offsets
// (row*256; V*256B = 256MB fits u32) so the hot loop's only long-latency
// op is the row gather itself.
#define BAGS_PER_CTA 16
#define SMEM_CAP 2048   // staged index capacity per CTA (u32 entries)

__global__ __launch_bounds__(256, 8)
void embag_mean_kernel(const void* __restrict__ indices_raw,
                       const void* __restrict__ offsets_raw,
                       const char* __restrict__ weight_bytes,
                       float* __restrict__ out,
                       int num_bags, long long total_indices) {
    __shared__ unsigned s_off[SMEM_CAP];

    const int tid  = threadIdx.x;
    const int lane = tid & 31;
    const int half = lane >> 4;
    const int sub  = lane & 15;
    const int warp_in_cta = tid >> 5;
    const int bag_first = blockIdx.x * BAGS_PER_CTA;
    const int bag = bag_first + 2 * warp_in_cta + half;

    // dtype detection (int64 vs int32): ids < 2^31 so an int64 LE buffer has
    // all odd 32-bit words zero; int32 has random ids there. Uniform result.
    const int* wprobe = (const int*)indices_raw;
    int allz = 1;
    #pragma unroll
    for (int k = 1; k < 9; k += 2) allz &= (__ldg(&wprobe[k]) == 0);
    const bool is64 = (allz != 0);

    const long long* __restrict__ idx64 = (const long long*)indices_raw;
    const int*       __restrict__ idx32 = (const int*)indices_raw;
    const long long* __restrict__ off64 = (const long long*)offsets_raw;
    const int*       __restrict__ off32 = (const int*)offsets_raw;

    // CTA-wide staged range: [cta_start, cta_end)
    const int last_bag = min(bag_first + BAGS_PER_CTA, num_bags);
    long long cta_start, cta_end;
    if (is64) {
        cta_start = __ldg(&off64[bag_first]);
        cta_end   = (last_bag < num_bags) ? __ldg(&off64[last_bag]) : total_indices;
    } else {
        cta_start = (long long)__ldg(&off32[bag_first]);
        cta_end   = (last_bag < num_bags) ? (long long)__ldg(&off32[last_bag]) : total_indices;
    }
    const long long cta_len = cta_end - cta_start;
    const bool use_smem = (cta_len <= SMEM_CAP);

    if (use_smem) {
        // Cooperative stage: convert indices -> row byte offsets in smem.
        if (is64) {
            for (int j = tid; j < (int)cta_len; j += blockDim.x)
                s_off[j] = (unsigned)__ldg(&idx64[cta_start + j]) << 8;
        } else {
            for (int j = tid; j < (int)cta_len; j += blockDim.x)
                s_off[j] = (unsigned)__ldg(&idx32[cta_start + j]) << 8;
        }
    }
    __syncthreads();

    if (bag >= num_bags) return;

    long long start, end;
    if (is64) {
        start = __ldg(&off64[bag]);
        end   = (bag + 1 < num_bags) ? __ldg(&off64[bag + 1]) : total_indices;
    } else {
        start = (long long)__ldg(&off32[bag]);
        end   = (bag + 1 < num_bags) ? (long long)__ldg(&off32[bag + 1]) : total_indices;
    }

    // Base pointer pre-offset by this lane's float4 column group.
    const char* __restrict__ wbase = weight_bytes + (unsigned)(sub * 16);

    float4 acc = make_float4(0.f, 0.f, 0.f, 0.f);

    if (use_smem) {
        const unsigned* so = s_off + (int)(start - cta_start);
        const int n = (int)(end - start);
        int j = 0;
        // 4 independent 512B row-pair gathers in flight; addresses from smem.
        for (; j + 4 <= n; j += 4) {
            const unsigned o0 = so[j], o1 = so[j + 1], o2 = so[j + 2], o3 = so[j + 3];
            float4 v0 = __ldg((const float4*)(wbase + o0));
            float4 v1 = __ldg((const float4*)(wbase + o1));
            float4 v2 = __ldg((const float4*)(wbase + o2));
            float4 v3 = __ldg((const float4*)(wbase + o3));
            acc.x += (v0.x + v1.x) + (v2.x + v3.x);
            acc.y += (v0.y + v1.y) + (v2.y + v3.y);
            acc.z += (v0.z + v1.z) + (v2.z + v3.z);
            acc.w += (v0.w + v1.w) + (v2.w + v3.w);
        }
        for (; j < n; ++j) {
            float4 v = __ldg((const float4*)(wbase + so[j]));
            acc.x += v.x; acc.y += v.y; acc.z += v.z; acc.w += v.w;
        }
    } else {
        // Fallback (oversized CTA range; never hit for L=50): direct global.
        for (long long i = start; i < end; ++i) {
            unsigned o = (is64 ? (unsigned)__ldg(&idx64[i])
                               : (unsigned)__ldg(&idx32[i])) << 8;
            float4 v = __ldg((const float4*)(wbase + o));
            acc.x += v.x; acc.y += v.y; acc.z += v.z; acc.w += v.w;
        }
    }

    const long long cnt = end - start;
    const float inv = 1.0f / (float)(cnt > 0 ? cnt : 1);
    acc.x *= inv; acc.y *= inv; acc.z *= inv; acc.w *= inv;

    ((float4*)out)[(size_t)bag * 16 + sub] = acc;
}

extern "C" void kernel_launch(void* const* d_in, const int* in_sizes, int n_in,
                              void* d_out, int out_size) {
    // metadata order: indices [T], offsets [B], weight [V*D]
    const void* indices = d_in[0];
    const void* offsets = d_in[1];
    const char* weight  = (const char*)d_in[2];
    float*      out     = (float*)d_out;

    const int       num_bags      = in_sizes[1];
    const long long total_indices = in_sizes[0];

    const int blocks = (num_bags + BAGS_PER_CTA - 1) / BAGS_PER_CTA;
    embag_mean_kernel<<<blocks, 256>>>(indices, offsets, weight, out,
                                       num_bags, total_indices);
}

// round 6
// speedup vs baseline: 1.1619x; 1.1619x over previous
#include <cuda_runtime.h>
#include <cstdint>

// embedding_bag(mode='mean'): B bags over a [V,64] fp32 table.
// One HALF-WARP per bag; sublane s (0..15) owns one float4 (cols 4s..4s+3).
// 16 lanes x 16B = one full 256B row per half-warp; each warp LDG.E.128
// fetches TWO rows (512B). Unroll x4 => 2KB outstanding per warp.
// 128-thread CTAs => 2048 CTAs: fine-grained balance across 152 SMs with a
// 16-CTA/SM residency cap (32 regs enforced) => single wave, high occupancy.
__global__ __launch_bounds__(128, 16)
void embag_mean_kernel(const void* __restrict__ indices_raw,
                       const void* __restrict__ offsets_raw,
                       const char* __restrict__ weight_bytes,
                       float* __restrict__ out,
                       int num_bags, long long total_indices) {
    const int warp_global = (int)((blockIdx.x * (unsigned)blockDim.x + threadIdx.x) >> 5);
    const int lane = threadIdx.x & 31;
    const int half = lane >> 4;        // which bag within the warp
    const int sub  = lane & 15;        // float4 column group within the row
    const int bag  = 2 * warp_global + half;
    if (bag >= num_bags) return;

    // Lane-fixed base pointer; row addresses become u32 BYTE offsets
    // (V*256B = 256MB fits u32) -> single-IMAD address math.
    const char* __restrict__ wbase = weight_bytes + (unsigned)(sub * 16);

    // Inline dtype detection (int64 vs int32 indices): ids < 2^31, so an
    // int64 LE buffer has every odd 32-bit word zero; an int32 buffer has
    // random ids there (P[all 4 zero] ~ 1e-24). Uniform -> no divergence.
    const int* wprobe = (const int*)indices_raw;
    int allz = 1;
    #pragma unroll
    for (int k = 1; k < 9; k += 2) allz &= (__ldg(&wprobe[k]) == 0);
    const bool is64 = (allz != 0);

    const long long* __restrict__ idx64 = (const long long*)indices_raw;
    const int*       __restrict__ idx32 = (const int*)indices_raw;
    const long long* __restrict__ off64 = (const long long*)offsets_raw;
    const int*       __restrict__ off32 = (const int*)offsets_raw;

    long long start, end;
    if (is64) {
        start = __ldg(&off64[bag]);
        end   = (bag + 1 < num_bags) ? __ldg(&off64[bag + 1]) : total_indices;
    } else {
        start = (long long)__ldg(&off32[bag]);
        end   = (bag + 1 < num_bags) ? (long long)__ldg(&off32[bag + 1]) : total_indices;
    }

    float4 acc = make_float4(0.f, 0.f, 0.f, 0.f);

    long long i = start;
    // Main loop: 4 independent 512B row-pair gathers in flight per warp.
    for (; i + 4 <= end; i += 4) {
        unsigned o0, o1, o2, o3;
        if (is64) {
            o0 = (unsigned)__ldg(&idx64[i    ]) << 8;
            o1 = (unsigned)__ldg(&idx64[i + 1]) << 8;
            o2 = (unsigned)__ldg(&idx64[i + 2]) << 8;
            o3 = (unsigned)__ldg(&idx64[i + 3]) << 8;
        } else {
            o0 = (unsigned)__ldg(&idx32[i    ]) << 8;
            o1 = (unsigned)__ldg(&idx32[i + 1]) << 8;
            o2 = (unsigned)__ldg(&idx32[i + 2]) << 8;
            o3 = (unsigned)__ldg(&idx32[i + 3]) << 8;
        }
        float4 v0 = __ldg((const float4*)(wbase + o0));
        float4 v1 = __ldg((const float4*)(wbase + o1));
        float4 v2 = __ldg((const float4*)(wbase + o2));
        float4 v3 = __ldg((const float4*)(wbase + o3));
        acc.x += (v0.x + v1.x) + (v2.x + v3.x);
        acc.y += (v0.y + v1.y) + (v2.y + v3.y);
        acc.z += (v0.z + v1.z) + (v2.z + v3.z);
        acc.w += (v0.w + v1.w) + (v2.w + v3.w);
    }
    // Scalar tail (<4 remaining).
    for (; i < end; ++i) {
        unsigned o = (is64 ? (unsigned)__ldg(&idx64[i])
                           : (unsigned)__ldg(&idx32[i])) << 8;
        float4 v = __ldg((const float4*)(wbase + o));
        acc.x += v.x; acc.y += v.y; acc.z += v.z; acc.w += v.w;
    }

    const long long cnt = end - start;
    const float inv = 1.0f / (float)(cnt > 0 ? cnt : 1);
    acc.x *= inv; acc.y *= inv; acc.z *= inv; acc.w *= inv;

    ((float4*)out)[(size_t)bag * 16 + sub] = acc;
}

extern "C" void kernel_launch(void* const* d_in, const int* in_sizes, int n_in,
                              void* d_out, int out_size) {
    // metadata order: indices [T], offsets [B], weight [V*D]
    const void* indices = d_in[0];
    const void* offsets = d_in[1];
    const char* weight  = (const char*)d_in[2];
    float*      out     = (float*)d_out;

    const int       num_bags      = in_sizes[1];
    const long long total_indices = in_sizes[0];

    // 2 bags per warp, 4 warps per block -> 8 bags per block.
    const int bags_per_block = 8;
    const int blocks = (num_bags + bags_per_block - 1) / bags_per_block;
    embag_mean_kernel<<<blocks, 128>>>(indices, offsets, weight, out,
                                       num_bags, total_indices);
}

// round 7
// speedup vs baseline: 1.2144x; 1.0451x over previous
#include <cuda_runtime.h>
#include <cstdint>

// embedding_bag(mode='mean'): B bags over a [V,64] fp32 table.
// One HALF-WARP per bag; sublane s (0..15) owns one float4 (cols 4s..4s+3).
// 16 lanes x 16B = one full 256B row per half-warp; each warp LDG.E.128
// fetches TWO rows (512B). Unroll x4 (2KB in flight per warp) + 2-wide tail
// so L=50 (12*4+2) never hits a serialized scalar loop.
// Row addresses are u32 BYTE offsets (V*256B = 256MB fits u32).
__global__ __launch_bounds__(256, 8)
void embag_mean_kernel(const void* __restrict__ indices_raw,
                       const void* __restrict__ offsets_raw,
                       const char* __restrict__ weight_bytes,
                       float* __restrict__ out,
                       int num_bags, long long total_indices) {
    const int warp_global = (int)((blockIdx.x * (unsigned)blockDim.x + threadIdx.x) >> 5);
    const int lane = threadIdx.x & 31;
    const int half = lane >> 4;        // bag within the warp
    const int sub  = lane & 15;        // float4 column group within the row
    const int bag  = 2 * warp_global + half;
    if (bag >= num_bags) return;

    const char* __restrict__ wbase = weight_bytes + (unsigned)(sub * 16);

    // Inline dtype detection (int64 vs int32 indices): ids < 2^31, so an
    // int64 LE buffer has every odd 32-bit word zero; an int32 buffer has
    // random nonzero ids there (P[all 4 zero] ~ 1e-24). Uniform result.
    const int* wprobe = (const int*)indices_raw;
    int allz = 1;
    #pragma unroll
    for (int k = 1; k < 9; k += 2) allz &= (__ldg(&wprobe[k]) == 0);
    const bool is64 = (allz != 0);

    const long long* __restrict__ idx64 = (const long long*)indices_raw;
    const int*       __restrict__ idx32 = (const int*)indices_raw;
    const long long* __restrict__ off64 = (const long long*)offsets_raw;
    const int*       __restrict__ off32 = (const int*)offsets_raw;

    long long start, end;
    if (is64) {
        start = __ldg(&off64[bag]);
        end   = (bag + 1 < num_bags) ? __ldg(&off64[bag + 1]) : total_indices;
    } else {
        start = (long long)__ldg(&off32[bag]);
        end   = (bag + 1 < num_bags) ? (long long)__ldg(&off32[bag + 1]) : total_indices;
    }

    float4 acc = make_float4(0.f, 0.f, 0.f, 0.f);

    long long i = start;
    // Main loop: 4 independent 512B row-pair gathers in flight per warp.
    #pragma unroll 1
    for (; i + 4 <= end; i += 4) {
        unsigned o0, o1, o2, o3;
        if (is64) {
            o0 = (unsigned)__ldg(&idx64[i    ]) << 8;
            o1 = (unsigned)__ldg(&idx64[i + 1]) << 8;
            o2 = (unsigned)__ldg(&idx64[i + 2]) << 8;
            o3 = (unsigned)__ldg(&idx64[i + 3]) << 8;
        } else {
            o0 = (unsigned)__ldg(&idx32[i    ]) << 8;
            o1 = (unsigned)__ldg(&idx32[i + 1]) << 8;
            o2 = (unsigned)__ldg(&idx32[i + 2]) << 8;
            o3 = (unsigned)__ldg(&idx32[i + 3]) << 8;
        }
        float4 v0 = __ldg((const float4*)(wbase + o0));
        float4 v1 = __ldg((const float4*)(wbase + o1));
        float4 v2 = __ldg((const float4*)(wbase + o2));
        float4 v3 = __ldg((const float4*)(wbase + o3));
        acc.x += (v0.x + v1.x) + (v2.x + v3.x);
        acc.y += (v0.y + v1.y) + (v2.y + v3.y);
        acc.z += (v0.z + v1.z) + (v2.z + v3.z);
        acc.w += (v0.w + v1.w) + (v2.w + v3.w);
    }
    // 2-wide tail (covers L % 4 == 2/3 without full serialization).
    if (i + 2 <= end) {
        unsigned o0, o1;
        if (is64) {
            o0 = (unsigned)__ldg(&idx64[i    ]) << 8;
            o1 = (unsigned)__ldg(&idx64[i + 1]) << 8;
        } else {
            o0 = (unsigned)__ldg(&idx32[i    ]) << 8;
            o1 = (unsigned)__ldg(&idx32[i + 1]) << 8;
        }
        float4 v0 = __ldg((const float4*)(wbase + o0));
        float4 v1 = __ldg((const float4*)(wbase + o1));
        acc.x += v0.x + v1.x;
        acc.y += v0.y + v1.y;
        acc.z += v0.z + v1.z;
        acc.w += v0.w + v1.w;
        i += 2;
    }
    if (i < end) {
        unsigned o = (is64 ? (unsigned)__ldg(&idx64[i])
                           : (unsigned)__ldg(&idx32[i])) << 8;
        float4 v = __ldg((const float4*)(wbase + o));
        acc.x += v.x; acc.y += v.y; acc.z += v.z; acc.w += v.w;
    }

    const long long cnt = end - start;
    const float inv = 1.0f / (float)(cnt > 0 ? cnt : 1);
    acc.x *= inv; acc.y *= inv; acc.z *= inv; acc.w *= inv;

    ((float4*)out)[(size_t)bag * 16 + sub] = acc;
}

extern "C" void kernel_launch(void* const* d_in, const int* in_sizes, int n_in,
                              void* d_out, int out_size) {
    // metadata order: indices [T], offsets [B], weight [V*D]
    const void* indices = d_in[0];
    const void* offsets = d_in[1];
    const char* weight  = (const char*)d_in[2];
    float*      out     = (float*)d_out;

    const int       num_bags      = in_sizes[1];
    const long long total_indices = in_sizes[0];

    // 2 bags per warp, 8 warps per block -> 16 bags per block.
    const int bags_per_block = 16;
    const int blocks = (num_bags + bags_per_block - 1) / bags_per_block;
    embag_mean_kernel<<<blocks, 256>>>(indices, offsets, weight, out,
                                       num_bags, total_indices);
}